// round 9
// baseline (speedup 1.0000x reference)
#include <cuda_runtime.h>
#include <cuda_bf16.h>

#define HH 1024
#define WW 1024
#define BB 16
#define PCOUNT (1024*1024)
#define PSTRIDE (2*PCOUNT)
#define NOCT 3              // octaves 3..7 weigh <=2^-15 -> ~1e-5 rel error
#define NBLK_PER_IMG 512    // noise blocks per image: (1024/32)*(1024/64)

__device__ float g_acc[BB * HH * WW];            // 64 MB accumulator (L2-resident)
__device__ int   g_bmn[BB * NBLK_PER_IMG];       // per-noise-block min (encoded)
__device__ int   g_bmx[BB * NBLK_PER_IMG];       // per-noise-block max (encoded)

__device__ __forceinline__ int fenc(float f) {
    int i = __float_as_int(f);
    return i >= 0 ? i : (i ^ 0x7fffffff);
}
__device__ __forceinline__ float fdec(int i) {
    return __int_as_float(i >= 0 ? i : (i ^ 0x7fffffff));
}
__device__ __forceinline__ float fade_f(float t) {
    return ((t * t) * t) * (t * (t * 6.0f - 15.0f) + 10.0f);
}
__device__ __forceinline__ void gcoef(int h, float& cx, float& cy, float& cz) {
    float s1 = (h & 1) ? -1.0f : 1.0f;
    float s2 = (h & 2) ? -1.0f : 1.0f;
    bool hx = h < 8;
    bool vy = h < 4;
    bool vx = ((h | 2) == 14);
    cx = (hx ? s1 : 0.0f) + (vx ? s2 : 0.0f);
    cy = (hx ? 0.0f : s1) + (vy ? s2 : 0.0f);
    cz = (!vy && !vx) ? s2 : 0.0f;
}

// Noise: warp = 32 cols x 8 rows; block = 32 cols x 64 rows. 3 octaves.
// Per-block lattice coeff tables built in smem (footprint <= 4x5 cells/octave).
__global__ void __launch_bounds__(256) k_noise(const int* __restrict__ p_all,
                                               const float* __restrict__ Xp,
                                               const float* __restrict__ Yp,
                                               const float* __restrict__ Zp) {
    int b = blockIdx.z;
    int lane = threadIdx.x & 31;
    int wid = threadIdx.x >> 5;
    int col0 = blockIdx.x * 32;
    int row0 = blockIdx.y * 64;
    int col = col0 + lane;

    __shared__ float4 stab[NOCT * 64];   // [o][iy_l(8)][ix_l(8)] coeffs (a,bx,by)
    __shared__ float4 sy[NOCT][64];      // (yf, ym, v, packed (o<<6)|(iy_l<<3))

    float X = Xp[0], Y = Yp[0];

    if (threadIdx.x < NOCT * 64) {
        int o    = threadIdx.x >> 6;
        int ix_l = threadIdx.x & 7;
        int iy_l = (threadIdx.x >> 3) & 7;
        float fr = (float)(1 << o);
        const int* __restrict__ p = p_all + (size_t)b * PSTRIDE;

        // --- per-block lattice table entry ---
        int cx = (int)floorf(__fdiv_rn((float)col0 + X, 100.0f) * fr) + ix_l;
        int cy = (int)floorf(__fdiv_rn((float)row0 + Y, 100.0f) * fr) + iy_l;
        float fz = __fdiv_rn(0.1f * (float)b + Zp[0], 100.0f) * fr;
        float flz = floorf(fz);
        float zf = fz - flz;
        float zm = zf - 1.0f;
        float w  = fade_f(zf);
        int Zi = ((int)flz) % 255;
        int Xi = cx % 255;
        int Yi = cy % 255;
        int pXi = __ldg(&p[Xi]);
        int A   = __ldg(&p[pXi + Yi]);
        int t   = A + Zi;
        int h0  = __ldg(&p[t]) & 15;
        int h1  = __ldg(&p[t + 1]) & 15;
        float cx0, cy0, cz0, cx1, cy1, cz1;
        gcoef(h0, cx0, cy0, cz0);
        gcoef(h1, cx1, cy1, cz1);
        float bxc = fmaf(w, cx1 - cx0, cx0);
        float byc = fmaf(w, cy1 - cy0, cy0);
        float t0 = cz0 * zf;
        float a  = fmaf(w, fmaf(cz1, zm, -t0), t0);
        stab[(o << 6) | (iy_l << 3) | ix_l] = make_float4(a, bxc, byc, 0.0f);

        // --- per-(octave,row) y data ---
        int i = threadIdx.x & 63;       // row-in-block
        int basey = (int)floorf(__fdiv_rn((float)row0 + Y, 100.0f) * fr);
        float fy = __fdiv_rn((float)(row0 + i) + Y, 100.0f) * fr;
        float fly = floorf(fy);
        float yf = fy - fly;
        int iy = (int)fly - basey;
        sy[o][i] = make_float4(yf, yf - 1.0f, fade_f(yf),
                               __int_as_float((o << 6) | (iy << 3)));
    }
    __syncthreads();

    float bx = __fdiv_rn((float)col + X, 100.0f);
    float bc0 = __fdiv_rn((float)col0 + X, 100.0f);

    float acc[8] = {0.f, 0.f, 0.f, 0.f, 0.f, 0.f, 0.f, 0.f};
    float freq = 1.0f;
    float camp = 1.0f;
#pragma unroll
    for (int o = 0; o < NOCT; o++) {
        float fx = bx * freq;
        float flx = floorf(fx);
        float xf = fx - flx;
        int ix = (int)flx - (int)floorf(bc0 * freq);   // local cell x
        float u = fade_f(xf);
        float xm = xf - 1.0f;

        float4 yd[8];
#pragma unroll
        for (int r = 0; r < 8; r++) yd[r] = sy[o][wid * 8 + r];
        int k0 = __float_as_int(yd[0].w);
        int k7 = __float_as_int(yd[7].w);

        const float4* rpA = stab + k0 + ix;
        float4 a00 = rpA[0], a10 = rpA[1], a01 = rpA[8], a11 = rpA[9];
        float A0 = fmaf(a00.y, xf, a00.x);
        float A1 = fmaf(a10.y, xm, a10.x);
        float A2 = fmaf(a01.y, xf, a01.x);
        float A3 = fmaf(a11.y, xm, a11.x);
        float P0A = fmaf(u, A1 - A0, A0);
        float Q0A = fmaf(u, a10.z - a00.z, a00.z);
        float P1A = fmaf(u, A3 - A2, A2);
        float Q1A = fmaf(u, a11.z - a01.z, a01.z);

        if (k0 == k7) {  // all 8 rows in one lattice row
#pragma unroll
            for (int r = 0; r < 8; r++) {
                float nx0 = fmaf(Q0A, yd[r].x, P0A);
                float nx1 = fmaf(Q1A, yd[r].y, P1A);
                float n   = fmaf(yd[r].z, nx1 - nx0, nx0);
                acc[r] = fmaf(n, camp, acc[r]);
            }
        } else {         // straddles exactly 2 lattice rows
            const float4* rpB = stab + k7 + ix;
            float4 b00 = rpB[0], b10 = rpB[1], b01 = rpB[8], b11 = rpB[9];
            float B0 = fmaf(b00.y, xf, b00.x);
            float B1 = fmaf(b10.y, xm, b10.x);
            float B2 = fmaf(b01.y, xf, b01.x);
            float B3 = fmaf(b11.y, xm, b11.x);
            float P0B = fmaf(u, B1 - B0, B0);
            float Q0B = fmaf(u, b10.z - b00.z, b00.z);
            float P1B = fmaf(u, B3 - B2, B2);
            float Q1B = fmaf(u, b11.z - b01.z, b01.z);
#pragma unroll
            for (int r = 0; r < 8; r++) {
                bool lo = (__float_as_int(yd[r].w) == k0);
                float P0 = lo ? P0A : P0B;
                float Q0 = lo ? Q0A : Q0B;
                float P1 = lo ? P1A : P1B;
                float Q1 = lo ? Q1A : Q1B;
                float nx0 = fmaf(Q0, yd[r].x, P0);
                float nx1 = fmaf(Q1, yd[r].y, P1);
                float n   = fmaf(yd[r].z, nx1 - nx0, nx0);
                acc[r] = fmaf(n, camp, acc[r]);
            }
        }
        freq *= 2.0f;
        camp *= 0.03125f;
    }

    size_t pbase = ((size_t)b << 20) + (size_t)(row0 + wid * 8) * WW + col;
#pragma unroll
    for (int r = 0; r < 8; r++) g_acc[pbase + (size_t)r * WW] = acc[r];

    float amn = acc[0], amx = acc[0];
#pragma unroll
    for (int r = 1; r < 8; r++) { amn = fminf(amn, acc[r]); amx = fmaxf(amx, acc[r]); }
    int mn = fenc(amn), mx = fenc(amx);
#pragma unroll
    for (int s = 16; s; s >>= 1) {
        mn = min(mn, __shfl_xor_sync(0xffffffffu, mn, s));
        mx = max(mx, __shfl_xor_sync(0xffffffffu, mx, s));
    }
    __shared__ int smn[8], smx[8];
    if (lane == 0) { smn[wid] = mn; smx[wid] = mx; }
    __syncthreads();
    if (threadIdx.x == 0) {
#pragma unroll
        for (int i = 1; i < 8; i++) { mn = min(mn, smn[i]); mx = max(mx, smx[i]); }
        int slot = b * NBLK_PER_IMG + blockIdx.y * 32 + blockIdx.x;
        g_bmn[slot] = mn;
        g_bmx[slot] = mx;
    }
}

// Normalize: each block first reduces its image's 512 per-block min/max slots.
// Thread handles 2 float4s. grid = (512, BB).
__global__ void __launch_bounds__(256) k_norm(float* __restrict__ out) {
    int b = blockIdx.y;
    int tid = threadIdx.x;

    int base = b * NBLK_PER_IMG;
    int mn = min(g_bmn[base + tid], g_bmn[base + tid + 256]);
    int mx = max(g_bmx[base + tid], g_bmx[base + tid + 256]);
#pragma unroll
    for (int s = 16; s; s >>= 1) {
        mn = min(mn, __shfl_xor_sync(0xffffffffu, mn, s));
        mx = max(mx, __shfl_xor_sync(0xffffffffu, mx, s));
    }
    __shared__ int smn[8], smx[8];
    __shared__ float s_mn, s_inv;
    if ((tid & 31) == 0) { smn[tid >> 5] = mn; smx[tid >> 5] = mx; }
    __syncthreads();
    if (tid == 0) {
#pragma unroll
        for (int i = 1; i < 8; i++) { mn = min(mn, smn[i]); mx = max(mx, smx[i]); }
        float fmn = fdec(mn), fmx = fdec(mx);
        s_mn = fmn;
        s_inv = 1.0f / (fmx - fmn);
    }
    __syncthreads();

    float fmn = s_mn, finv = s_inv;
    const float4* __restrict__ src = reinterpret_cast<const float4*>(g_acc) + ((size_t)b << 18);
    float4* __restrict__ dst = reinterpret_cast<float4*>(out) + ((size_t)b << 18);
#pragma unroll
    for (int j = 0; j < 2; j++) {
        int idx = blockIdx.x * 512 + j * 256 + tid;
        float4 a = __ldcs(&src[idx]);
        a.x = (a.x - fmn) * finv;
        a.y = (a.y - fmn) * finv;
        a.z = (a.z - fmn) * finv;
        a.w = (a.w - fmn) * finv;
        __stcs(&dst[idx], a);
    }
}

extern "C" void kernel_launch(void* const* d_in, const int* in_sizes, int n_in,
                              void* d_out, int out_size) {
    const int* p_all  = (const int*)d_in[0];
    const float* X    = (const float*)d_in[1];
    const float* Y    = (const float*)d_in[2];
    const float* Z    = (const float*)d_in[3];
    float* out        = (float*)d_out;

    dim3 gn(WW / 32, HH / 64, BB);
    k_noise<<<gn, 256>>>(p_all, X, Y, Z);
    dim3 gz(512, BB);
    k_norm<<<gz, 256>>>(out);
}